// round 14
// baseline (speedup 1.0000x reference)
#include <cuda_runtime.h>
#include <cfloat>

#define BB   32
#define NN   2048
#define FF   3
#define HH   64
#define KK   16
#define OUTD 128
#define BCH  4     // batches per L2-resident d2 chunk (4 * 16 MB = 64 MB < 126 MB L2)
#define NT   (NN / 128)          // 16 tiles per dim for dist128
#define NTRI (NT * (NT + 1) / 2) // 136 upper-triangle tiles
#define PCN  8     // nodes per precompute/postmat block
#define L0Q  8     // query nodes per layer-0 knn block

// ---------------- scratch (static device globals; no allocations) ----------------
__device__ float g_d2[(size_t)BCH * NN * NN];  // 64 MB, reused every chunk -> stays in L2
__device__ float g_sq[BB * NN];                // squared norms
__device__ float g_a [BB * NN * HH];           // a_i = x_i @ w1[:D] + b1
__device__ float g_p [BB * NN * HH];           // p_i = x_i @ w1[D:]
__device__ float g_sm[BB * NN * HH];           // mean-relu output of current layer
__device__ float g_h1[BB * NN * HH];           // feature ping
__device__ float g_h2[BB * NN * HH];           // feature pong

// order-preserving float->u32 map (total order matches IEEE < for all finite values)
__device__ __forceinline__ unsigned ordkey(float f) {
    const unsigned u = __float_as_uint(f);
    return (u & 0x80000000u) ? ~u : (u | 0x80000000u);
}

// ---------------- packed f32x2 helpers (B300 FFMA2 path, per SASS_QUICKREF) ----------------
__device__ __forceinline__ unsigned long long pack2(float lo, float hi) {
    unsigned long long d;
    asm("mov.b64 %0, {%1, %2};" : "=l"(d) : "r"(__float_as_uint(lo)), "r"(__float_as_uint(hi)));
    return d;
}
__device__ __forceinline__ void unpack2(unsigned long long v, float& lo, float& hi) {
    unsigned l, h;
    asm("mov.b64 {%0, %1}, %2;" : "=r"(l), "=r"(h) : "l"(v));
    lo = __uint_as_float(l); hi = __uint_as_float(h);
}
#define FMA2(acc, a, b) \
    asm("fma.rn.f32x2 %0, %1, %2, %0;" : "+l"(acc) : "l"(a), "l"(b))

// ---------------- layer-0 precompute: a, p from x (D=3) ----------------
template<int D>
__global__ __launch_bounds__(PCN * HH)
void precompute_kernel(const float* __restrict__ x,
                       const float* __restrict__ w1,
                       const float* __restrict__ b1)
{
    const int tid  = threadIdx.x;            // 0 .. 511
    const int g    = tid >> 6;               // node group 0..7
    const int h    = tid & 63;               // 0 .. 63
    const int node = blockIdx.x * PCN + g;   // 0 .. B*N-1

    __shared__ float sw1[2 * D * HH];
    __shared__ float sx[PCN][HH];

    for (int idx = tid; idx < 2 * D * HH; idx += PCN * HH) sw1[idx] = w1[idx];
    if (h < D) sx[g][h] = x[(size_t)node * D + h];
    __syncthreads();

    float av = b1[h];
    float pv = 0.f;
#pragma unroll
    for (int d = 0; d < D; d++) {
        const float xv = sx[g][d];
        av += xv * sw1[d * HH + h];
        pv += xv * sw1[(D + d) * HH + h];
    }
    g_a[(size_t)node * HH + h] = av;
    g_p[(size_t)node * HH + h] = pv;
}

// ---------------- postmat: h = sm @ wo + bo; optionally next-layer a, p, sq ----------------
// 8 nodes per 512-thread block; wo (and w1next) staged ONCE in shared.
template<bool NEXT>
__global__ __launch_bounds__(PCN * HH)
void postmat_kernel(const float* __restrict__ wo,  const float* __restrict__ bo,
                    const float* __restrict__ w1n, const float* __restrict__ b1n,
                    float* __restrict__ feat)
{
    const int tid  = threadIdx.x;
    const int g    = tid >> 6;               // node group 0..7
    const int o    = tid & 63;
    const int node = blockIdx.x * PCN + g;

    __shared__ float swo[HH * HH];                       // 16 KB
    __shared__ float sw1[NEXT ? 2 * HH * HH : 1];        // 32 KB when staging next w1
    __shared__ float ssm[PCN][HH];
    __shared__ float sh [PCN][HH];
    __shared__ float sprod[PCN][HH];

    for (int idx = tid; idx < HH * HH; idx += PCN * HH) swo[idx] = wo[idx];
    if (NEXT)
        for (int idx = tid; idx < 2 * HH * HH; idx += PCN * HH) sw1[idx] = w1n[idx];
    ssm[g][o] = g_sm[(size_t)node * HH + o];
    __syncthreads();

    float hv = bo[o];
#pragma unroll 16
    for (int hh = 0; hh < HH; hh++) hv += ssm[g][hh] * swo[hh * HH + o];
    feat[(size_t)node * HH + o] = hv;

    if (NEXT) {
        sh[g][o]    = hv;
        sprod[g][o] = hv * hv;
        __syncthreads();

        float av = b1n[o];
        float pv = 0.f;
#pragma unroll 16
        for (int d = 0; d < HH; d++) {
            const float xv = sh[g][d];
            av += xv * sw1[d * HH + o];
            pv += xv * sw1[(HH + d) * HH + o];
        }
        g_a[(size_t)node * HH + o] = av;
        g_p[(size_t)node * HH + o] = pv;

#pragma unroll
        for (int s = 32; s > 0; s >>= 1) {
            if (o < s) sprod[g][o] += sprod[g][o + s];
            __syncthreads();
        }
        if (o == 0) g_sq[node] = sprod[g][0];
    }
}

// ---------------- hierarchical top-16 (REDUX-based) + EdgeConv mean-relu ----------------
// 256 threads; thread t owns row elements j = t*8 + e held in v[8].
// Stage 1: per-warp top-16 (lexicographic (val, idx) order, no barriers).
// Stage 2: warp 0 merges 8x16 candidates -> global top-16 (same set+order as jax.lax.top_k).
// Emits sm[h] = mean_k relu(a_i + p_j - p_i); the wo matvec happens in postmat_kernel.
// Phase boundaries are barrier-separated, so shared arrays may be reused by
// back-to-back calls from the same block (multi-query loops).
__device__ __forceinline__ void select_and_aggregate(
    float (&v)[8], int b, int i, float* __restrict__ smout)
{
    const int tid  = threadIdx.x;
    const int lane = tid & 31;
    const int w    = tid >> 5;

    __shared__ unsigned cval[8 * KK];
    __shared__ int      cidx[8 * KK];
    __shared__ int      ssel[KK];
    __shared__ float    spart[KK * 68];   // padded partials: spart[k*68 + h]

    unsigned ok[8];
#pragma unroll
    for (int e = 0; e < 8; e++) ok[e] = ordkey(v[e]);

    // ---- stage 1: per-warp top-16, no block syncs ----
    unsigned popped = 0;
    unsigned hk = 0xffffffffu; int he = -1;
#pragma unroll
    for (int e = 0; e < 8; e++)                  // ascending e + strict < => lowest j on ties
        if (ok[e] < hk) { hk = ok[e]; he = e; }

#pragma unroll 1
    for (int p = 0; p < KK; p++) {
        const unsigned key = hk;                 // UINT_MAX sentinel when exhausted
        const unsigned m   = __reduce_min_sync(0xffffffffu, key);
        const unsigned myj = (he >= 0 && key == m) ? (unsigned)(tid * 8 + he) : 0x7fffffffu;
        const unsigned jm  = __reduce_min_sync(0xffffffffu, myj);
        if (lane == 0) { cval[w * KK + p] = m; cidx[w * KK + p] = (int)jm; }
        if (myj == jm && he >= 0 && key == m) {  // unique owner pops + recomputes head
            popped |= 1u << he;
            hk = 0xffffffffu; he = -1;
#pragma unroll
            for (int e = 0; e < 8; e++)
                if (!((popped >> e) & 1u) && ok[e] < hk) { hk = ok[e]; he = e; }
        }
    }
    __syncthreads();

    // ---- stage 2: warp 0 merges 128 candidates (4 per lane; each lane's list is a
    // contiguous slice of one warp's lexicographically ascending output) ----
    if (w == 0) {
        unsigned mk[4]; int mi[4];
#pragma unroll
        for (int q = 0; q < 4; q++) { mk[q] = cval[lane * 4 + q]; mi[q] = cidx[lane * 4 + q]; }
        unsigned mpop = 0;
        unsigned mhk = 0xffffffffu; int mhe = -1;
#pragma unroll
        for (int q = 0; q < 4; q++)              // ascending slice + strict < => lex min
            if (mk[q] < mhk) { mhk = mk[q]; mhe = q; }

#pragma unroll 1
        for (int p = 0; p < KK; p++) {
            const unsigned key = mhk;
            const unsigned m   = __reduce_min_sync(0xffffffffu, key);
            const unsigned myj = (mhe >= 0 && key == m) ? (unsigned)mi[mhe] : 0x7fffffffu;
            const unsigned jm  = __reduce_min_sync(0xffffffffu, myj);
            if (lane == 0) ssel[p] = (int)jm;
            if (myj == jm && mhe >= 0 && key == m) {
                mpop |= 1u << mhe;
                mhk = 0xffffffffu; mhe = -1;
#pragma unroll
                for (int q = 0; q < 4; q++)
                    if (!((mpop >> q) & 1u) && mk[q] < mhk) { mhk = mk[q]; mhe = q; }
            }
        }
    }
    __syncthreads();

    // ---- edge message: spart[k][h] = relu(a_i + p_j(k) - p_i), 256 threads ----
    {
        const int k  = tid >> 4;            // neighbor slot 0..15
        const int h4 = (tid & 15) * 4;      // 0,4,...,60
        const int j  = ssel[k];
        const size_t ioff = ((size_t)b * NN + i) * HH;
        const float4 a4 = *(const float4*)&g_a[ioff + h4];
        const float4 p4 = *(const float4*)&g_p[ioff + h4];
        const float4 pj = *(const float4*)&g_p[((size_t)b * NN + j) * HH + h4];
        float* sp = &spart[k * 68 + h4];
        sp[0] = fmaxf(a4.x + pj.x - p4.x, 0.f);
        sp[1] = fmaxf(a4.y + pj.y - p4.y, 0.f);
        sp[2] = fmaxf(a4.z + pj.z - p4.z, 0.f);
        sp[3] = fmaxf(a4.w + pj.w - p4.w, 0.f);
    }
    __syncthreads();

    if (tid < HH) {
        float accv = 0.f;
#pragma unroll
        for (int k = 0; k < KK; k++) accv += spart[k * 68 + tid];
        smout[((size_t)b * NN + i) * HH + tid] = accv * (1.f / KK);
    }
}

// ---------------- layer 0 fused kNN (D=3): 8 queries per block ----------------
// Neighbor coords read ONCE per block into registers; 8 query selections run
// sequentially, amortizing the 24 KB batch read 8x (kills redundant L2 traffic).
__global__ void knn_l0_kernel(const float* __restrict__ x, float* __restrict__ smout)
{
    const int g0  = blockIdx.x * L0Q;   // first query node of this block
    const int b   = blockIdx.y;
    const int tid = threadIdx.x;        // 256

    const float* __restrict__ xb = x + (size_t)b * NN * FF;

    __shared__ float4 sxq4[6];          // 8 queries x 3 coords = 24 floats
    const float* sxq = (const float*)sxq4;
    if (tid < 6) sxq4[tid] = ((const float4*)(xb + (size_t)g0 * FF))[tid];

    // 8 neighbors' coords: 24 contiguous floats = 6 float4 (start 96B-aligned per thread)
    float c[24];
    {
        const float4* src = (const float4*)(xb + (size_t)tid * 8 * FF);
#pragma unroll
        for (int q = 0; q < 6; q++) {
            const float4 t = src[q];
            c[q * 4 + 0] = t.x; c[q * 4 + 1] = t.y; c[q * 4 + 2] = t.z; c[q * 4 + 3] = t.w;
        }
    }
    __syncthreads();

#pragma unroll 1
    for (int q = 0; q < L0Q; q++) {
        const float xi0 = sxq[q * 3 + 0];
        const float xi1 = sxq[q * 3 + 1];
        const float xi2 = sxq[q * 3 + 2];
        float v[8];
#pragma unroll
        for (int e = 0; e < 8; e++) {
            const float d0 = xi0 - c[e * 3 + 0];
            const float d1 = xi1 - c[e * 3 + 1];
            const float d2v = xi2 - c[e * 3 + 2];
            v[e] = d0 * d0 + d1 * d1 + d2v * d2v;
        }
        select_and_aggregate(v, b, g0 + q, smout);
    }
}

// ---------------- D=64 distance kernel: 128x128 tile, BK=8, 8x8 micro-tile ----------------
// Packed f32x2 FMA (FFMA2) inner loop; rb operands loaded as pre-packed u64 pairs
// straight from shared (16B-aligned). Per-lane fma.rn => numerics identical to scalar.
// Upper-triangle tiles only (ti <= tj); off-diagonal tiles write both [i][j] and [j][i].
// Double-buffered smem; d2 indexed by LOCAL batch (chunk-reused region stays in L2).
__global__ __launch_bounds__(256, 2)
void dist128_kernel(const float* __restrict__ x, int b0)
{
    const int bl = blockIdx.y;          // local batch in chunk
    const int b  = b0 + bl;

    // map linear upper-triangle index -> (ti, tj), ti <= tj
    int ti = 0, rem = blockIdx.x, rowlen = NT;
    while (rem >= rowlen) { rem -= rowlen; ti++; rowlen--; }
    const int tj = ti + rem;
    const int i0 = ti * 128;
    const int j0 = tj * 128;

    const float* __restrict__ xb = x + (size_t)b * NN * HH;

    __shared__ float As[2][8][132];
    __shared__ float Bs[2][8][132];

    const int tid = threadIdx.x;   // 256
    const int tx  = tid & 15;
    const int ty  = tid >> 4;

    const int si  = tid >> 1;          // 0..127 tile row
    const int sk  = (tid & 1) * 4;     // k offset within 8-chunk

    const float* gA = &xb[(size_t)(i0 + si) * HH + sk];
    const float* gB = &xb[(size_t)(j0 + si) * HH + sk];

    unsigned long long acc2[8][4] = {};   // packed f32x2 accumulators (0ull == {0.f,0.f})

    {
        const float4 av = *(const float4*)gA;
        const float4 bv = *(const float4*)gB;
        As[0][sk + 0][si] = av.x; As[0][sk + 1][si] = av.y; As[0][sk + 2][si] = av.z; As[0][sk + 3][si] = av.w;
        Bs[0][sk + 0][si] = bv.x; Bs[0][sk + 1][si] = bv.y; Bs[0][sk + 2][si] = bv.z; Bs[0][sk + 3][si] = bv.w;
    }
    __syncthreads();

#pragma unroll
    for (int kt = 0; kt < HH / 8; kt++) {
        const int cur = kt & 1;
        float4 av, bv;
        if (kt + 1 < HH / 8) {          // prefetch next chunk BEFORE compute
            av = *(const float4*)(gA + (kt + 1) * 8);
            bv = *(const float4*)(gB + (kt + 1) * 8);
        }
#pragma unroll
        for (int k = 0; k < 8; k++) {
            const float4 a0 = *(const float4*)&As[cur][k][ty * 4];
            const float4 a1 = *(const float4*)&As[cur][k][64 + ty * 4];
            // rb pairs pre-packed by layout: 16B-aligned LDS.128 as 2x u64
            const ulonglong2 rb01 = *(const ulonglong2*)&Bs[cur][k][tx * 4];
            const ulonglong2 rb23 = *(const ulonglong2*)&Bs[cur][k][64 + tx * 4];
            const unsigned long long rbp[4] = {rb01.x, rb01.y, rb23.x, rb23.y};
            const float ra[8] = {a0.x, a0.y, a0.z, a0.w, a1.x, a1.y, a1.z, a1.w};
#pragma unroll
            for (int m = 0; m < 8; m++) {
                const unsigned long long rap = pack2(ra[m], ra[m]);
#pragma unroll
                for (int q = 0; q < 4; q++)
                    FMA2(acc2[m][q], rap, rbp[q]);
            }
        }
        if (kt + 1 < HH / 8) {
            const int nxt = cur ^ 1;
            As[nxt][sk + 0][si] = av.x; As[nxt][sk + 1][si] = av.y; As[nxt][sk + 2][si] = av.z; As[nxt][sk + 3][si] = av.w;
            Bs[nxt][sk + 0][si] = bv.x; Bs[nxt][sk + 1][si] = bv.y; Bs[nxt][sk + 2][si] = bv.z; Bs[nxt][sk + 3][si] = bv.w;
            __syncthreads();
        }
    }

    // unpack accumulators
    float acc[8][8];
#pragma unroll
    for (int m = 0; m < 8; m++)
#pragma unroll
        for (int q = 0; q < 4; q++)
            unpack2(acc2[m][q], acc[m][2 * q], acc[m][2 * q + 1]);

    const float* __restrict__ sqb = g_sq + b * NN;
    float* __restrict__ d2b = g_d2 + (size_t)bl * NN * NN;

    float sj[8];
#pragma unroll
    for (int n = 0; n < 4; n++) {
        sj[n]     = sqb[j0 + tx * 4 + n];
        sj[4 + n] = sqb[j0 + 64 + tx * 4 + n];
    }
#pragma unroll
    for (int m = 0; m < 8; m++) {
        const int i  = i0 + ((m < 4) ? (ty * 4 + m) : (64 + ty * 4 + (m - 4)));
        const float si_ = sqb[i];
#pragma unroll
        for (int n = 0; n < 8; n++)
            acc[m][n] = si_ + sj[n] - 2.f * acc[m][n];
    }
#pragma unroll
    for (int m = 0; m < 8; m++) {
        const int i = i0 + ((m < 4) ? (ty * 4 + m) : (64 + ty * 4 + (m - 4)));
        float4 v0 = {acc[m][0], acc[m][1], acc[m][2], acc[m][3]};
        float4 v1 = {acc[m][4], acc[m][5], acc[m][6], acc[m][7]};
        *(float4*)&d2b[(size_t)i * NN + j0 + tx * 4]      = v0;
        *(float4*)&d2b[(size_t)i * NN + j0 + 64 + tx * 4] = v1;
    }
    if (ti != tj) {   // symmetric transposed writes
#pragma unroll
        for (int n = 0; n < 8; n++) {
            const int j = j0 + ((n < 4) ? (tx * 4 + n) : (64 + tx * 4 + (n - 4)));
            float4 t0 = {acc[0][n], acc[1][n], acc[2][n], acc[3][n]};
            float4 t1 = {acc[4][n], acc[5][n], acc[6][n], acc[7][n]};
            *(float4*)&d2b[(size_t)j * NN + i0 + ty * 4]      = t0;
            *(float4*)&d2b[(size_t)j * NN + i0 + 64 + ty * 4] = t1;
        }
    }
}

// ---------------- per-row top-16 from d2 (layers 1-2) ----------------
__global__ void knn_agg_kernel(float* __restrict__ smout, int b0)
{
    const int i   = blockIdx.x;
    const int bl  = blockIdx.y;
    const int b   = b0 + bl;
    const int tid = threadIdx.x;   // 256

    const float4* __restrict__ row4 =
        (const float4*)(g_d2 + ((size_t)bl * NN + i) * NN);
    const float4 r0 = row4[tid * 2];
    const float4 r1 = row4[tid * 2 + 1];
    float v[8] = {r0.x, r0.y, r0.z, r0.w, r1.x, r1.y, r1.z, r1.w};

    select_and_aggregate(v, b, i, smout);
}

// ---------------- global mean pool + final MLP ----------------
__global__ void final_kernel(const float* __restrict__ hin,
                             const float* __restrict__ fw1, const float* __restrict__ fb1,
                             const float* __restrict__ fw2, const float* __restrict__ fb2,
                             float* __restrict__ out)
{
    const int b   = blockIdx.x;
    const int tid = threadIdx.x;   // 256
    const int h   = tid & 63;
    const int s   = tid >> 6;

    const float* __restrict__ hb = hin + (size_t)b * NN * HH;
    float acc = 0.f;
    for (int n = s; n < NN; n += 4) acc += hb[(size_t)n * HH + h];

    __shared__ float red[4][HH];
    __shared__ float sg[HH];
    __shared__ float st[HH];
    red[s][h] = acc;
    __syncthreads();
    if (tid < HH)
        sg[tid] = (red[0][tid] + red[1][tid] + red[2][tid] + red[3][tid]) * (1.f / NN);
    __syncthreads();
    if (tid < HH) {
        float r = fb1[tid];
#pragma unroll 16
        for (int hh = 0; hh < HH; hh++) r += sg[hh] * fw1[hh * HH + tid];
        st[tid] = fmaxf(r, 0.f);
    }
    __syncthreads();
    if (tid < OUTD) {
        float r = fb2[tid];
#pragma unroll 16
        for (int o = 0; o < HH; o++) r += st[o] * fw2[o * OUTD + tid];
        out[b * OUTD + tid] = r;
    }
}

// ---------------- launch ----------------
extern "C" void kernel_launch(void* const* d_in, const int* in_sizes, int n_in,
                              void* d_out, int out_size)
{
    const float* x  = (const float*)d_in[0];
    const float* w1[3] = {(const float*)d_in[1], (const float*)d_in[5], (const float*)d_in[9]};
    const float* b1[3] = {(const float*)d_in[2], (const float*)d_in[6], (const float*)d_in[10]};
    const float* wo[3] = {(const float*)d_in[3], (const float*)d_in[7], (const float*)d_in[11]};
    const float* bo[3] = {(const float*)d_in[4], (const float*)d_in[8], (const float*)d_in[12]};
    const float* fw1 = (const float*)d_in[13];
    const float* fb1 = (const float*)d_in[14];
    const float* fw2 = (const float*)d_in[15];
    const float* fb2 = (const float*)d_in[16];
    float* out = (float*)d_out;

    float *gh1 = nullptr, *gh2 = nullptr, *gsm = nullptr;
    cudaGetSymbolAddress((void**)&gh1, g_h1);   // host-side query, not a stream op
    cudaGetSymbolAddress((void**)&gh2, g_h2);
    cudaGetSymbolAddress((void**)&gsm, g_sm);

    const dim3 distGrid1(NTRI, BCH);
    const dim3 knnGrid(NN, BCH);
    const dim3 l0Grid(NN / L0Q, BB);
    const int  pmGrid = BB * NN / PCN;

    // ---- layer 0 (D = 3): fused direct-distance kNN, no d2 ----
    precompute_kernel<FF><<<pmGrid, PCN * HH>>>(x, w1[0], b1[0]);
    knn_l0_kernel<<<l0Grid, 256>>>(x, gsm);
    // h1 = sm @ wo0 + bo0; also a, p, sq for layer 1
    postmat_kernel<true><<<pmGrid, PCN * HH>>>(wo[0], bo[0], w1[1], b1[1], gh1);

    // ---- layer 1 (D = 64) ----
    for (int b0 = 0; b0 < BB; b0 += BCH) {
        dist128_kernel<<<distGrid1, 256>>>(gh1, b0);
        knn_agg_kernel<<<knnGrid, 256>>>(gsm, b0);
    }
    postmat_kernel<true><<<pmGrid, PCN * HH>>>(wo[1], bo[1], w1[2], b1[2], gh2);

    // ---- layer 2 (D = 64) ----
    for (int b0 = 0; b0 < BB; b0 += BCH) {
        dist128_kernel<<<distGrid1, 256>>>(gh2, b0);
        knn_agg_kernel<<<knnGrid, 256>>>(gsm, b0);
    }
    postmat_kernel<false><<<pmGrid, PCN * HH>>>(wo[2], bo[2], nullptr, nullptr, gh1);

    // ---- pool + head ----
    final_kernel<<<BB, 256>>>(gh1, fw1, fb1, fw2, fb2, out);
}

// round 17
// speedup vs baseline: 1.2497x; 1.2497x over previous
#include <cuda_runtime.h>
#include <cfloat>

#define BB   32
#define NN   2048
#define FF   3
#define HH   64
#define KK   16
#define OUTD 128
#define BCH  4     // batches per L2-resident d2 chunk (4 * 16 MB = 64 MB < 126 MB L2)
#define NT   (NN / 128)          // 16 tiles per dim for dist128
#define NTRI (NT * (NT + 1) / 2) // 136 upper-triangle tiles
#define PCN  8     // nodes per precompute/postmat block
#define L0Q  8     // query nodes per layer-0 knn block

// ---------------- scratch (static device globals; no allocations) ----------------
__device__ float g_d2[(size_t)BCH * NN * NN];  // 64 MB, reused every chunk -> stays in L2
__device__ float g_sq[BB * NN];                // squared norms
__device__ float g_a [BB * NN * HH];           // a_i = x_i @ w1[:D] + b1
__device__ float g_p [BB * NN * HH];           // p_i = x_i @ w1[D:]
__device__ float g_sm[BB * NN * HH];           // mean-relu output of current layer
__device__ float g_h1[BB * NN * HH];           // feature ping
__device__ float g_h2[BB * NN * HH];           // feature pong

// order-preserving float->u32 map (total order matches IEEE < for all finite values)
__device__ __forceinline__ unsigned ordkey(float f) {
    const unsigned u = __float_as_uint(f);
    return (u & 0x80000000u) ? ~u : (u | 0x80000000u);
}

// ---------------- packed f32x2 helpers (B300 FFMA2 path, per SASS_QUICKREF) ----------------
__device__ __forceinline__ unsigned long long pack2(float lo, float hi) {
    unsigned long long d;
    asm("mov.b64 %0, {%1, %2};" : "=l"(d) : "r"(__float_as_uint(lo)), "r"(__float_as_uint(hi)));
    return d;
}
__device__ __forceinline__ void unpack2(unsigned long long v, float& lo, float& hi) {
    unsigned l, h;
    asm("mov.b64 {%0, %1}, %2;" : "=r"(l), "=r"(h) : "l"(v));
    lo = __uint_as_float(l); hi = __uint_as_float(h);
}
#define FMA2(acc, a, b) \
    asm("fma.rn.f32x2 %0, %1, %2, %0;" : "+l"(acc) : "l"(a), "l"(b))

// ---------------- layer-0 precompute: a, p from x (D=3) ----------------
template<int D>
__global__ __launch_bounds__(PCN * HH)
void precompute_kernel(const float* __restrict__ x,
                       const float* __restrict__ w1,
                       const float* __restrict__ b1)
{
    const int tid  = threadIdx.x;            // 0 .. 511
    const int g    = tid >> 6;               // node group 0..7
    const int h    = tid & 63;               // 0 .. 63
    const int node = blockIdx.x * PCN + g;   // 0 .. B*N-1

    __shared__ float sw1[2 * D * HH];
    __shared__ float sx[PCN][HH];

    for (int idx = tid; idx < 2 * D * HH; idx += PCN * HH) sw1[idx] = w1[idx];
    if (h < D) sx[g][h] = x[(size_t)node * D + h];
    __syncthreads();

    float av = b1[h];
    float pv = 0.f;
#pragma unroll
    for (int d = 0; d < D; d++) {
        const float xv = sx[g][d];
        av += xv * sw1[d * HH + h];
        pv += xv * sw1[(D + d) * HH + h];
    }
    g_a[(size_t)node * HH + h] = av;
    g_p[(size_t)node * HH + h] = pv;
}

// ---------------- postmat: h = sm @ wo + bo; optionally next-layer a, p, sq ----------------
// 8 nodes per 512-thread block; wo (and w1next) staged ONCE in shared.
template<bool NEXT>
__global__ __launch_bounds__(PCN * HH)
void postmat_kernel(const float* __restrict__ wo,  const float* __restrict__ bo,
                    const float* __restrict__ w1n, const float* __restrict__ b1n,
                    float* __restrict__ feat)
{
    const int tid  = threadIdx.x;
    const int g    = tid >> 6;               // node group 0..7
    const int o    = tid & 63;
    const int node = blockIdx.x * PCN + g;

    __shared__ float swo[HH * HH];                       // 16 KB
    __shared__ float sw1[NEXT ? 2 * HH * HH : 1];        // 32 KB when staging next w1
    __shared__ float ssm[PCN][HH];
    __shared__ float sh [PCN][HH];
    __shared__ float sprod[PCN][HH];

    for (int idx = tid; idx < HH * HH; idx += PCN * HH) swo[idx] = wo[idx];
    if (NEXT)
        for (int idx = tid; idx < 2 * HH * HH; idx += PCN * HH) sw1[idx] = w1n[idx];
    ssm[g][o] = g_sm[(size_t)node * HH + o];
    __syncthreads();

    float hv = bo[o];
#pragma unroll 16
    for (int hh = 0; hh < HH; hh++) hv += ssm[g][hh] * swo[hh * HH + o];
    feat[(size_t)node * HH + o] = hv;

    if (NEXT) {
        sh[g][o]    = hv;
        sprod[g][o] = hv * hv;
        __syncthreads();

        float av = b1n[o];
        float pv = 0.f;
#pragma unroll 16
        for (int d = 0; d < HH; d++) {
            const float xv = sh[g][d];
            av += xv * sw1[d * HH + o];
            pv += xv * sw1[(HH + d) * HH + o];
        }
        g_a[(size_t)node * HH + o] = av;
        g_p[(size_t)node * HH + o] = pv;

#pragma unroll
        for (int s = 32; s > 0; s >>= 1) {
            if (o < s) sprod[g][o] += sprod[g][o + s];
            __syncthreads();
        }
        if (o == 0) g_sq[node] = sprod[g][0];
    }
}

// ---------------- top-16 + EdgeConv mean-relu (sorted-queue + parallel-rank) ----------------
// 256 threads; thread t owns row elements j = t*8 + e, packed as u64 (ordkey<<11 | j)
// so u64 order == lexicographic (value, index) order == jax.lax.top_k order.
// Stage 1 (per warp, no barriers): thread-local 8-sort (Batcher, 19 comparators), then
//   16 pops; per pass ONE REDUX + ballot: lane order == j order, so lowest holder lane
//   is the lexicographic winner; owner pops by register shift.
// Stage 2 (all warps): exact parallel rank of the 128 candidates (2 threads/candidate,
//   all-pairs u64 compares); rank<16 -> ssel[rank]=j. Exact same set + order as pop-min.
__device__ __forceinline__ void select_and_aggregate(
    float (&v)[8], int b, int i, float* __restrict__ smout)
{
    const int tid  = threadIdx.x;
    const int lane = tid & 31;
    const int w    = tid >> 5;

    __shared__ unsigned long long cq[8 * KK];   // 128 packed candidates
    __shared__ unsigned char      srank[256];   // partial ranks (<=64)
    __shared__ int                ssel[KK];
    __shared__ float              spart[KK * 68];

    unsigned long long q[8];
#pragma unroll
    for (int e = 0; e < 8; e++)
        q[e] = ((unsigned long long)ordkey(v[e]) << 11) | (unsigned)(tid * 8 + e);

    // Batcher odd-even merge sort, 19 comparators, ascending
#define CSW(a, c) { if (q[a] > q[c]) { unsigned long long t_ = q[a]; q[a] = q[c]; q[c] = t_; } }
    CSW(0,1); CSW(2,3); CSW(4,5); CSW(6,7);
    CSW(0,2); CSW(1,3); CSW(4,6); CSW(5,7);
    CSW(1,2); CSW(5,6);
    CSW(0,4); CSW(1,5); CSW(2,6); CSW(3,7);
    CSW(2,4); CSW(3,5);
    CSW(1,2); CSW(3,4); CSW(5,6);
#undef CSW

    // ---- stage 1: per-warp top-16, no block syncs ----
#pragma unroll 1
    for (int p = 0; p < KK; p++) {
        const unsigned key = (unsigned)(q[0] >> 11);
        const unsigned m   = __reduce_min_sync(0xffffffffu, key);
        const unsigned msk = __ballot_sync(0xffffffffu, key == m);
        const int src = __ffs(msk) - 1;
        if (lane == src) {
            cq[w * KK + p] = q[0];
            q[0] = q[1]; q[1] = q[2]; q[2] = q[3]; q[3] = q[4];
            q[4] = q[5]; q[5] = q[6]; q[6] = q[7]; q[7] = ~0ull;
        }
    }
    __syncthreads();

    // ---- stage 2: exact parallel rank of 128 candidates ----
    {
        const int c    = tid >> 1;
        const int half = tid & 1;
        const unsigned long long qc = cq[c];
        const unsigned long long* base = &cq[half * 64];
        int r = 0;
#pragma unroll 16
        for (int it = 0; it < 64; it++)
            r += (base[it] < qc) ? 1 : 0;
        srank[tid] = (unsigned char)r;
    }
    __syncthreads();
    if (tid < 128) {
        const int rank = (int)srank[2 * tid] + (int)srank[2 * tid + 1];
        if (rank < KK) ssel[rank] = (int)(cq[tid] & 0x7FFull);
    }
    __syncthreads();

    // ---- edge message: spart[k][h] = relu(a_i + p_j(k) - p_i), 256 threads ----
    {
        const int k  = tid >> 4;            // neighbor slot 0..15
        const int h4 = (tid & 15) * 4;      // 0,4,...,60
        const int j  = ssel[k];
        const size_t ioff = ((size_t)b * NN + i) * HH;
        const float4 a4 = *(const float4*)&g_a[ioff + h4];
        const float4 p4 = *(const float4*)&g_p[ioff + h4];
        const float4 pj = *(const float4*)&g_p[((size_t)b * NN + j) * HH + h4];
        float* sp = &spart[k * 68 + h4];
        sp[0] = fmaxf(a4.x + pj.x - p4.x, 0.f);
        sp[1] = fmaxf(a4.y + pj.y - p4.y, 0.f);
        sp[2] = fmaxf(a4.z + pj.z - p4.z, 0.f);
        sp[3] = fmaxf(a4.w + pj.w - p4.w, 0.f);
    }
    __syncthreads();

    if (tid < HH) {
        float accv = 0.f;
#pragma unroll
        for (int k = 0; k < KK; k++) accv += spart[k * 68 + tid];
        smout[((size_t)b * NN + i) * HH + tid] = accv * (1.f / KK);
    }
    __syncthreads();   // protect cq/ssel/spart reuse across back-to-back calls
}

// ---------------- layer 0 fused kNN (D=3): 8 queries per block ----------------
__global__ void knn_l0_kernel(const float* __restrict__ x, float* __restrict__ smout)
{
    const int g0  = blockIdx.x * L0Q;   // first query node of this block
    const int b   = blockIdx.y;
    const int tid = threadIdx.x;        // 256

    const float* __restrict__ xb = x + (size_t)b * NN * FF;

    __shared__ float4 sxq4[6];          // 8 queries x 3 coords = 24 floats
    const float* sxq = (const float*)sxq4;
    if (tid < 6) sxq4[tid] = ((const float4*)(xb + (size_t)g0 * FF))[tid];

    float c[24];
    {
        const float4* src = (const float4*)(xb + (size_t)tid * 8 * FF);
#pragma unroll
        for (int q = 0; q < 6; q++) {
            const float4 t = src[q];
            c[q * 4 + 0] = t.x; c[q * 4 + 1] = t.y; c[q * 4 + 2] = t.z; c[q * 4 + 3] = t.w;
        }
    }
    __syncthreads();

#pragma unroll 1
    for (int q = 0; q < L0Q; q++) {
        const float xi0 = sxq[q * 3 + 0];
        const float xi1 = sxq[q * 3 + 1];
        const float xi2 = sxq[q * 3 + 2];
        float v[8];
#pragma unroll
        for (int e = 0; e < 8; e++) {
            const float d0 = xi0 - c[e * 3 + 0];
            const float d1 = xi1 - c[e * 3 + 1];
            const float d2v = xi2 - c[e * 3 + 2];
            v[e] = d0 * d0 + d1 * d1 + d2v * d2v;
        }
        select_and_aggregate(v, b, g0 + q, smout);
    }
}

// ---------------- D=64 distance kernel: 128x128 tile, BK=8, FFMA2 inner loop ----------------
__global__ __launch_bounds__(256, 2)
void dist128_kernel(const float* __restrict__ x, int b0)
{
    const int bl = blockIdx.y;          // local batch in chunk
    const int b  = b0 + bl;

    int ti = 0, rem = blockIdx.x, rowlen = NT;
    while (rem >= rowlen) { rem -= rowlen; ti++; rowlen--; }
    const int tj = ti + rem;
    const int i0 = ti * 128;
    const int j0 = tj * 128;

    const float* __restrict__ xb = x + (size_t)b * NN * HH;

    __shared__ float As[2][8][132];
    __shared__ float Bs[2][8][132];

    const int tid = threadIdx.x;   // 256
    const int tx  = tid & 15;
    const int ty  = tid >> 4;

    const int si  = tid >> 1;          // 0..127 tile row
    const int sk  = (tid & 1) * 4;     // k offset within 8-chunk

    const float* gA = &xb[(size_t)(i0 + si) * HH + sk];
    const float* gB = &xb[(size_t)(j0 + si) * HH + sk];

    unsigned long long acc2[8][4] = {};   // packed f32x2 accumulators

    {
        const float4 av = *(const float4*)gA;
        const float4 bv = *(const float4*)gB;
        As[0][sk + 0][si] = av.x; As[0][sk + 1][si] = av.y; As[0][sk + 2][si] = av.z; As[0][sk + 3][si] = av.w;
        Bs[0][sk + 0][si] = bv.x; Bs[0][sk + 1][si] = bv.y; Bs[0][sk + 2][si] = bv.z; Bs[0][sk + 3][si] = bv.w;
    }
    __syncthreads();

#pragma unroll
    for (int kt = 0; kt < HH / 8; kt++) {
        const int cur = kt & 1;
        float4 av, bv;
        if (kt + 1 < HH / 8) {
            av = *(const float4*)(gA + (kt + 1) * 8);
            bv = *(const float4*)(gB + (kt + 1) * 8);
        }
#pragma unroll
        for (int k = 0; k < 8; k++) {
            const float4 a0 = *(const float4*)&As[cur][k][ty * 4];
            const float4 a1 = *(const float4*)&As[cur][k][64 + ty * 4];
            const ulonglong2 rb01 = *(const ulonglong2*)&Bs[cur][k][tx * 4];
            const ulonglong2 rb23 = *(const ulonglong2*)&Bs[cur][k][64 + tx * 4];
            const unsigned long long rbp[4] = {rb01.x, rb01.y, rb23.x, rb23.y};
            const float ra[8] = {a0.x, a0.y, a0.z, a0.w, a1.x, a1.y, a1.z, a1.w};
#pragma unroll
            for (int m = 0; m < 8; m++) {
                const unsigned long long rap = pack2(ra[m], ra[m]);
#pragma unroll
                for (int qn = 0; qn < 4; qn++)
                    FMA2(acc2[m][qn], rap, rbp[qn]);
            }
        }
        if (kt + 1 < HH / 8) {
            const int nxt = cur ^ 1;
            As[nxt][sk + 0][si] = av.x; As[nxt][sk + 1][si] = av.y; As[nxt][sk + 2][si] = av.z; As[nxt][sk + 3][si] = av.w;
            Bs[nxt][sk + 0][si] = bv.x; Bs[nxt][sk + 1][si] = bv.y; Bs[nxt][sk + 2][si] = bv.z; Bs[nxt][sk + 3][si] = bv.w;
            __syncthreads();
        }
    }

    float acc[8][8];
#pragma unroll
    for (int m = 0; m < 8; m++)
#pragma unroll
        for (int qn = 0; qn < 4; qn++)
            unpack2(acc2[m][qn], acc[m][2 * qn], acc[m][2 * qn + 1]);

    const float* __restrict__ sqb = g_sq + b * NN;
    float* __restrict__ d2b = g_d2 + (size_t)bl * NN * NN;

    float sj[8];
#pragma unroll
    for (int n = 0; n < 4; n++) {
        sj[n]     = sqb[j0 + tx * 4 + n];
        sj[4 + n] = sqb[j0 + 64 + tx * 4 + n];
    }
#pragma unroll
    for (int m = 0; m < 8; m++) {
        const int i  = i0 + ((m < 4) ? (ty * 4 + m) : (64 + ty * 4 + (m - 4)));
        const float si_ = sqb[i];
#pragma unroll
        for (int n = 0; n < 8; n++)
            acc[m][n] = si_ + sj[n] - 2.f * acc[m][n];
    }
#pragma unroll
    for (int m = 0; m < 8; m++) {
        const int i = i0 + ((m < 4) ? (ty * 4 + m) : (64 + ty * 4 + (m - 4)));
        float4 v0 = {acc[m][0], acc[m][1], acc[m][2], acc[m][3]};
        float4 v1 = {acc[m][4], acc[m][5], acc[m][6], acc[m][7]};
        *(float4*)&d2b[(size_t)i * NN + j0 + tx * 4]      = v0;
        *(float4*)&d2b[(size_t)i * NN + j0 + 64 + tx * 4] = v1;
    }
    if (ti != tj) {
#pragma unroll
        for (int n = 0; n < 8; n++) {
            const int j = j0 + ((n < 4) ? (tx * 4 + n) : (64 + tx * 4 + (n - 4)));
            float4 t0 = {acc[0][n], acc[1][n], acc[2][n], acc[3][n]};
            float4 t1 = {acc[4][n], acc[5][n], acc[6][n], acc[7][n]};
            *(float4*)&d2b[(size_t)j * NN + i0 + ty * 4]      = t0;
            *(float4*)&d2b[(size_t)j * NN + i0 + 64 + ty * 4] = t1;
        }
    }
}

// ---------------- per-row top-16 from d2 (layers 1-2) ----------------
__global__ void knn_agg_kernel(float* __restrict__ smout, int b0)
{
    const int i   = blockIdx.x;
    const int bl  = blockIdx.y;
    const int b   = b0 + bl;
    const int tid = threadIdx.x;   // 256

    const float4* __restrict__ row4 =
        (const float4*)(g_d2 + ((size_t)bl * NN + i) * NN);
    const float4 r0 = row4[tid * 2];
    const float4 r1 = row4[tid * 2 + 1];
    float v[8] = {r0.x, r0.y, r0.z, r0.w, r1.x, r1.y, r1.z, r1.w};

    select_and_aggregate(v, b, i, smout);
}

// ---------------- profiling alignment no-op (shifts ncu -s 5 capture onto knn_agg) ----------
__global__ void noop_kernel() {}

// ---------------- global mean pool + final MLP ----------------
__global__ void final_kernel(const float* __restrict__ hin,
                             const float* __restrict__ fw1, const float* __restrict__ fb1,
                             const float* __restrict__ fw2, const float* __restrict__ fb2,
                             float* __restrict__ out)
{
    const int b   = blockIdx.x;
    const int tid = threadIdx.x;   // 256
    const int h   = tid & 63;
    const int s   = tid >> 6;

    const float* __restrict__ hb = hin + (size_t)b * NN * HH;
    float acc = 0.f;
    for (int n = s; n < NN; n += 4) acc += hb[(size_t)n * HH + h];

    __shared__ float red[4][HH];
    __shared__ float sg[HH];
    __shared__ float st[HH];
    red[s][h] = acc;
    __syncthreads();
    if (tid < HH)
        sg[tid] = (red[0][tid] + red[1][tid] + red[2][tid] + red[3][tid]) * (1.f / NN);
    __syncthreads();
    if (tid < HH) {
        float r = fb1[tid];
#pragma unroll 16
        for (int hh = 0; hh < HH; hh++) r += sg[hh] * fw1[hh * HH + tid];
        st[tid] = fmaxf(r, 0.f);
    }
    __syncthreads();
    if (tid < OUTD) {
        float r = fb2[tid];
#pragma unroll 16
        for (int o = 0; o < HH; o++) r += st[o] * fw2[o * OUTD + tid];
        out[b * OUTD + tid] = r;
    }
}

// ---------------- launch ----------------
extern "C" void kernel_launch(void* const* d_in, const int* in_sizes, int n_in,
                              void* d_out, int out_size)
{
    const float* x  = (const float*)d_in[0];
    const float* w1[3] = {(const float*)d_in[1], (const float*)d_in[5], (const float*)d_in[9]};
    const float* b1[3] = {(const float*)d_in[2], (const float*)d_in[6], (const float*)d_in[10]};
    const float* wo[3] = {(const float*)d_in[3], (const float*)d_in[7], (const float*)d_in[11]};
    const float* bo[3] = {(const float*)d_in[4], (const float*)d_in[8], (const float*)d_in[12]};
    const float* fw1 = (const float*)d_in[13];
    const float* fb1 = (const float*)d_in[14];
    const float* fw2 = (const float*)d_in[15];
    const float* fb2 = (const float*)d_in[16];
    float* out = (float*)d_out;

    float *gh1 = nullptr, *gh2 = nullptr, *gsm = nullptr;
    cudaGetSymbolAddress((void**)&gh1, g_h1);   // host-side query, not a stream op
    cudaGetSymbolAddress((void**)&gh2, g_h2);
    cudaGetSymbolAddress((void**)&gsm, g_sm);

    const dim3 distGrid1(NTRI, BCH);
    const dim3 knnGrid(NN, BCH);
    const dim3 l0Grid(NN / L0Q, BB);
    const int  pmGrid = BB * NN / PCN;

    // ---- layer 0 (D = 3): fused direct-distance kNN, no d2 ----
    precompute_kernel<FF><<<pmGrid, PCN * HH>>>(x, w1[0], b1[0]);      // launch 1
    knn_l0_kernel<<<l0Grid, 256>>>(x, gsm);                            // launch 2
    postmat_kernel<true><<<pmGrid, PCN * HH>>>(wo[0], bo[0], w1[1], b1[1], gh1);  // launch 3
    noop_kernel<<<1, 32>>>();                                          // launch 4 (aims ncu)

    // ---- layer 1 (D = 64) ----
    for (int b0 = 0; b0 < BB; b0 += BCH) {
        dist128_kernel<<<distGrid1, 256>>>(gh1, b0);                   // launch 5, ...
        knn_agg_kernel<<<knnGrid, 256>>>(gsm, b0);                     // launch 6 <- profiled
    }
    postmat_kernel<true><<<pmGrid, PCN * HH>>>(wo[1], bo[1], w1[2], b1[2], gh2);

    // ---- layer 2 (D = 64) ----
    for (int b0 = 0; b0 < BB; b0 += BCH) {
        dist128_kernel<<<distGrid1, 256>>>(gh2, b0);
        knn_agg_kernel<<<knnGrid, 256>>>(gsm, b0);
    }
    postmat_kernel<false><<<pmGrid, PCN * HH>>>(wo[2], bo[2], nullptr, nullptr, gh1);

    // ---- pool + head ----
    final_kernel<<<BB, 256>>>(gh1, fw1, fb1, fw2, fb2, out);
}